// round 13
// baseline (speedup 1.0000x reference)
#include <cuda_runtime.h>
#include <cuda_bf16.h>
#include <cstdint>

#define LRELU_SLOPE 0.2f
#define BN_EPS 1e-5f

#define NIMG 82
#define NQIMG 32
#define CH 64
#define H1 84
#define H2 42
#define H3 21
#define LL 441
#define MM 2205

// ---------------- scratch (device globals; no allocs allowed) ----------------
__device__ float g_A[(size_t)NIMG*CH*H1*H1];
__device__ float g_Bf[(size_t)NIMG*CH*H2*H2];
__device__ float g_Cf[(size_t)NIMG*CH*H2*H2];
__device__ float g_qn[(size_t)NQIMG*LL*CH];
__device__ float g_sn[(size_t)2*5*MM*CH];
__device__ float g_bnsum4[4*128*2];            // [layer][grp*64+c][{s,s2}]
__device__ float g_WT[64*9*64];                // conv1 weights [ci*9+k][co]
// bf16-split weight fragments: [cc(4)][s(9)][nt(8)][lane(32)][reg(2)]
__device__ uint32_t g_W2h[18432];
__device__ uint32_t g_W2l[18432];
__device__ uint32_t g_W3h[18432];
__device__ uint32_t g_W3l[18432];
__device__ uint32_t g_W4h[18432];
__device__ uint32_t g_W4l[18432];

__device__ __forceinline__ float lrelu(float x){ return x >= 0.f ? x : LRELU_SLOPE*x; }

__device__ __forceinline__ void ins3(float v, float& t0, float& t1, float& t2){
    if (v > t2) {
        float s  = fminf(t0, v);
        t0 = fmaxf(t0, v);
        float s2 = fminf(t1, s);
        t1 = fmaxf(t1, s);
        t2 = fmaxf(t2, s2);
    }
}

// split fp32 pair into bf16x2 hi + bf16x2 lo (v = hi + lo, error ~2^-18)
__device__ __forceinline__ void split2(float vx, float vy, uint32_t& hi, uint32_t& lo){
    __nv_bfloat162 h = __floats2bfloat162_rn(vx, vy);
    float hx = __bfloat162float(h.x);
    float hy = __bfloat162float(h.y);
    __nv_bfloat162 l = __floats2bfloat162_rn(vx - hx, vy - hy);
    hi = *reinterpret_cast<uint32_t*>(&h);
    lo = *reinterpret_cast<uint32_t*>(&l);
}

#define MMA_BF16(C, A, b0, b1) \
    asm volatile("mma.sync.aligned.m16n8k16.row.col.f32.bf16.bf16.f32 " \
        "{%0,%1,%2,%3},{%4,%5,%6,%7},{%8,%9},{%0,%1,%2,%3};" \
        : "+f"((C)[0]), "+f"((C)[1]), "+f"((C)[2]), "+f"((C)[3]) \
        : "r"((A)[0]), "r"((A)[1]), "r"((A)[2]), "r"((A)[3]), "r"(b0), "r"(b1))

#define MMA_TF32(C, A, b0, b1) \
    asm volatile("mma.sync.aligned.m16n8k8.row.col.f32.tf32.tf32.f32 " \
        "{%0,%1,%2,%3},{%4,%5,%6,%7},{%8,%9},{%0,%1,%2,%3};" \
        : "+f"((C)[0]), "+f"((C)[1]), "+f"((C)[2]), "+f"((C)[3]) \
        : "r"((A)[0]), "r"((A)[1]), "r"((A)[2]), "r"((A)[3]), "r"(b0), "r"(b1))

// BN scale/shift from per-layer raw sums
__device__ __forceinline__ void bn_sc(int layer, int gc, float HW, float gamma, float beta,
                                      float& sc, float& sh){
    float s  = g_bnsum4[(layer*128 + gc)*2 + 0];
    float s2 = g_bnsum4[(layer*128 + gc)*2 + 1];
    float cnt = ((gc >= 64) ? 50.f : 32.f) * HW;
    float mean = s / cnt;
    float var = s2 / cnt - mean*mean;
    float inv = rsqrtf(var + BN_EPS);
    sc = gamma * inv;
    sh = beta - mean * sc;
}

// ---------------- prep: zero + conv1 wtrans + conv2/3/4 frag pack ------------
__device__ __forceinline__ void frag_compute(const float* __restrict__ W, int i,
                                             uint32_t& hi, uint32_t& lo){
    int r  = i & 1;
    int t  = (i >> 1) & 31;
    int nt = (i >> 6) & 7;
    int rem = i >> 9;
    int s  = rem % 9;
    int cc = rem / 9;
    int q = t & 3, nn = t >> 2;
    int ci = cc*16 + 2*q + 8*r;
    int co = nt*8 + nn;
    float v0 = W[((size_t)co*64 + ci    )*9 + s];
    float v1 = W[((size_t)co*64 + ci + 1)*9 + s];
    split2(v0, v1, hi, lo);
}

__global__ void prep_kernel(float* out, const float* __restrict__ W1,
                            const float* __restrict__ W2, const float* __restrict__ W3,
                            const float* __restrict__ W4){
    int bx = blockIdx.x, tid = threadIdx.x;
    if (bx == 0) {
        if (tid < 160) out[tid] = 0.f;
        for (int i = tid; i < 4*128*2; i += 256) g_bnsum4[i] = 0.f;
    } else if (bx < 8) {
        int i = (bx-1)*256 + tid;
        if (i < 3*9*64) {
            int co = i & 63, r = i >> 6;
            int ci = r / 9, k = r % 9;
            g_WT[i] = W1[(size_t)co*3*9 + ci*9 + k];
        }
    } else if (bx < 80) {
        int i = (bx-8)*256 + tid;
        uint32_t hi, lo; frag_compute(W2, i, hi, lo);
        g_W2h[i] = hi; g_W2l[i] = lo;
    } else if (bx < 152) {
        int i = (bx-80)*256 + tid;
        uint32_t hi, lo; frag_compute(W3, i, hi, lo);
        g_W3h[i] = hi; g_W3l[i] = lo;
    } else {
        int i = (bx-152)*256 + tid;
        uint32_t hi, lo; frag_compute(W4, i, hi, lo);
        g_W4h[i] = hi; g_W4l[i] = lo;
    }
}

// ---------------- conv1: 3->64 @ 84x84, pad 1 (writes g_A) ----------------
__global__ void __launch_bounds__(256,3) conv1_kernel(const float* __restrict__ query,
                                                      const float* __restrict__ support) {
    __shared__ float swt[27*32];
    __shared__ float sin[3*18*18];
    int n = blockIdx.z, coH = blockIdx.y;
    int bx = blockIdx.x;
    int x0 = (bx % 6) * 16, y0 = (bx / 6) * 16;
    int tid = threadIdx.x;
    int tx = tid & 15, ty = tid >> 4;
    for (int i = tid; i < 864; i += 256) {
        int kk = i >> 5, co = i & 31;
        swt[i] = g_WT[kk*64 + coH*32 + co];
    }
    const float* img = (n < NQIMG) ? (query + (size_t)n*3*H1*H1)
                                   : (support + (size_t)(n-NQIMG)*3*H1*H1);
    for (int i = tid; i < 972; i += 256) {
        int ci = i / 324, rem = i % 324;
        int yy = rem / 18, xx = rem % 18;
        int gy = y0 - 1 + yy, gx = x0 - 1 + xx;
        sin[i] = (gy>=0 && gy<H1 && gx>=0 && gx<H1) ? img[(size_t)ci*H1*H1 + gy*H1 + gx] : 0.f;
    }
    __syncthreads();
    float r[27];
    #pragma unroll
    for (int ci=0;ci<3;ci++)
      #pragma unroll
      for (int dy=0;dy<3;dy++)
        #pragma unroll
        for (int dx=0;dx<3;dx++)
          r[ci*9+dy*3+dx] = sin[ci*324 + (ty+dy)*18 + (tx+dx)];
    float acc[32];
    #pragma unroll
    for (int i=0;i<32;i++) acc[i]=0.f;
    const float4* swt4 = (const float4*)swt;
    #pragma unroll
    for (int kk=0; kk<27; kk++) {
        float v = r[kk];
        #pragma unroll
        for (int c4=0; c4<8; c4++) {
            float4 w = swt4[kk*8 + c4];
            acc[c4*4+0] += w.x*v;
            acc[c4*4+1] += w.y*v;
            acc[c4*4+2] += w.z*v;
            acc[c4*4+3] += w.w*v;
        }
    }
    int y = y0+ty, x = x0+tx;
    if (y < H1 && x < H1) {
        size_t obase = ((size_t)n*CH + coH*32)*H1*H1 + (size_t)y*H1 + x;
        #pragma unroll 4
        for (int co=0; co<32; co++) g_A[obase + (size_t)co*H1*H1] = acc[co];
    }
}

// ---------------- BN partial stats -> g_bnsum4[layer] (16 y-slices) ----------
__global__ void bn_part_kernel(int srcSel, int HW, int layer){
    const float* src = (srcSel==0) ? g_A : (srcSel==1) ? g_Bf : g_Cf;
    int gc = blockIdx.x;
    int grp = gc >> 6, c = gc & 63;
    int slice = blockIdx.y;
    int n0, n1;
    if (!grp) { n0 = slice*2; n1 = n0+2; }
    else { n0 = 32 + (50*slice)/16; n1 = 32 + (50*(slice+1))/16; }
    float s = 0.f, s2 = 0.f;
    if ((HW & 3) == 0) {
        int m = HW >> 2;
        for (int n=n0; n<n1; n++) {
            const float4* p = (const float4*)(src + ((size_t)n*CH + c)*HW);
            for (int i=threadIdx.x; i<m; i+=256) {
                float4 v = p[i];
                s  += v.x + v.y + v.z + v.w;
                s2 += v.x*v.x + v.y*v.y + v.z*v.z + v.w*v.w;
            }
        }
    } else {
        for (int n=n0; n<n1; n++) {
            const float* p = src + ((size_t)n*CH + c)*HW;
            for (int i=threadIdx.x; i<HW; i+=256) {
                float v = p[i]; s += v; s2 += v*v;
            }
        }
    }
    __shared__ float sh1[256], sh2[256];
    sh1[threadIdx.x]=s; sh2[threadIdx.x]=s2;
    __syncthreads();
    for (int ofs=128; ofs>0; ofs>>=1) {
        if (threadIdx.x<ofs){ sh1[threadIdx.x]+=sh1[threadIdx.x+ofs]; sh2[threadIdx.x]+=sh2[threadIdx.x+ofs]; }
        __syncthreads();
    }
    if (threadIdx.x==0) {
        atomicAdd(&g_bnsum4[(layer*128+gc)*2+0], sh1[0]);
        atomicAdd(&g_bnsum4[(layer*128+gc)*2+1], sh2[0]);
    }
}

// ---------------- pool0: BN+LReLU+2x2 maxpool, 84->42, 2 outputs/thread ------
__global__ void bn_pool0_pair(const float* __restrict__ gamma, const float* __restrict__ beta) {
    int nc = blockIdx.y;
    int n = nc >> 6, c = nc & 63;
    int grp = (n < NQIMG) ? 0 : 1;
    float sc, sh;
    bn_sc(0, grp*64+c, (float)(H1*H1), gamma[c], beta[c], sc, sh);
    const float* base = g_A + (size_t)nc*H1*H1;
    float* obase = g_Bf + (size_t)nc*H2*H2;
    int idx = blockIdx.x*256 + threadIdx.x;      // 0..881 (42 rows x 21 col-pairs)
    if (idx >= 42*21) return;
    int y = idx / 21, xp = idx % 21;
    float4 a = *(const float4*)(base + (2*y)*H1 + 4*xp);
    float4 b = *(const float4*)(base + (2*y+1)*H1 + 4*xp);
    float o0 = fmaxf(fmaxf(lrelu(a.x*sc+sh), lrelu(a.y*sc+sh)),
                     fmaxf(lrelu(b.x*sc+sh), lrelu(b.y*sc+sh)));
    float o1 = fmaxf(fmaxf(lrelu(a.z*sc+sh), lrelu(a.w*sc+sh)),
                     fmaxf(lrelu(b.z*sc+sh), lrelu(b.w*sc+sh)));
    float2 o = {o0, o1};
    *(float2*)(obase + idx*2) = o;
}

// ---------------- pool1: BN+LReLU+2x2 maxpool, 42->21 -----------------------
__global__ void bn_pool1(const float* __restrict__ gamma, const float* __restrict__ beta) {
    int nc = blockIdx.y;
    int n = nc >> 6, c = nc & 63;
    int grp = (n < NQIMG) ? 0 : 1;
    float sc, sh;
    bn_sc(1, grp*64+c, (float)(H2*H2), gamma[c], beta[c], sc, sh);
    const float* base = g_Cf + (size_t)nc*H2*H2;
    float* obase = g_A + (size_t)nc*H3*H3;
    int idx = blockIdx.x*256 + threadIdx.x;
    if (idx >= H3*H3) return;
    int y = idx / H3, x = idx % H3;
    const float* p = base + (2*y)*H2 + 2*x;
    float2 r0 = *(const float2*)p;
    float2 r1 = *(const float2*)(p + H2);
    float a = lrelu(r0.x*sc+sh);
    float b = lrelu(r0.y*sc+sh);
    float c2 = lrelu(r1.x*sc+sh);
    float d = lrelu(r1.y*sc+sh);
    obase[idx] = fmaxf(fmaxf(a,b), fmaxf(c2,d));
}

// ---------------- conv2 (bf16 pre-split tensor core implicit GEMM) -----------
__global__ void __launch_bounds__(256,3) conv2_tc() {
    extern __shared__ uint32_t smu[];
    uint32_t* sInH = smu;                 // 2916
    uint32_t* sInL = sInH + 2916;         // 2916
    uint32_t* sWh  = sInL + 2916;         // 4608 (byte off 23328, %16==0)
    uint32_t* sWl  = sWh + 4608;          // 4608  -> total 60192 B
    int n = blockIdx.y;
    int bx = blockIdx.x;
    int x0 = (bx % 3) * 16, y0 = (bx / 3) * 16;
    int tid = threadIdx.x;
    int w = tid >> 5, lane = tid & 31, g = lane >> 2, q4 = lane & 3;
    float acc[2][8][4];
    #pragma unroll
    for (int i=0;i<2;i++)
      #pragma unroll
      for (int nt=0;nt<8;nt++)
        #pragma unroll
        for (int r=0;r<4;r++) acc[i][nt][r]=0.f;
    const float* ibase = g_Bf + (size_t)n*CH*H2*H2;
    for (int cc=0; cc<4; cc++) {
        __syncthreads();
        for (int i=tid; i<2592; i+=256) {
            int cp = i / 324, pos = i % 324;
            int yy = pos / 18, xx = pos % 18;
            int gy = y0 - 1 + yy, gx = x0 - 1 + xx;
            float v0 = 0.f, v1 = 0.f;
            if (gy>=0 && gy<H2 && gx>=0 && gx<H2) {
                const float* pp = ibase + (size_t)(cc*16 + 2*cp)*H2*H2 + gy*H2 + gx;
                v0 = pp[0];
                v1 = pp[H2*H2];
            }
            uint32_t hi, lo;
            split2(v0, v1, hi, lo);
            sInH[pos*9 + cp] = hi;
            sInL[pos*9 + cp] = lo;
        }
        {
            const uint4* sh = (const uint4*)(g_W2h + cc*4608);
            const uint4* sl = (const uint4*)(g_W2l + cc*4608);
            uint4* dh = (uint4*)sWh;
            uint4* dl = (uint4*)sWl;
            for (int i=tid; i<1152; i+=256) { dh[i]=sh[i]; dl[i]=sl[i]; }
        }
        __syncthreads();
        for (int s=0; s<9; s++) {
            int dy = s / 3, dx = s - 3*dy;
            uint32_t Ah[2][4], Al[2][4];
            #pragma unroll
            for (int i=0;i<2;i++) {
                int yy = 2*w + i + dy;
                const uint32_t* pH0 = &sInH[(yy*18 + g + dx)*9];
                const uint32_t* pH1 = &sInH[(yy*18 + g + 8 + dx)*9];
                const uint32_t* pL0 = &sInL[(yy*18 + g + dx)*9];
                const uint32_t* pL1 = &sInL[(yy*18 + g + 8 + dx)*9];
                Ah[i][0] = pH0[q4];   Ah[i][1] = pH1[q4];
                Ah[i][2] = pH0[q4+4]; Ah[i][3] = pH1[q4+4];
                Al[i][0] = pL0[q4];   Al[i][1] = pL1[q4];
                Al[i][2] = pL0[q4+4]; Al[i][3] = pL1[q4+4];
            }
            #pragma unroll
            for (int nt=0; nt<8; nt++) {
                int wb = s*512 + nt*64 + lane*2;
                uint32_t bh0 = sWh[wb], bh1 = sWh[wb+1];
                uint32_t bl0 = sWl[wb], bl1 = sWl[wb+1];
                #pragma unroll
                for (int i=0;i<2;i++) {
                    MMA_BF16(acc[i][nt], Ah[i], bh0, bh1);
                    MMA_BF16(acc[i][nt], Ah[i], bl0, bl1);
                    MMA_BF16(acc[i][nt], Al[i], bh0, bh1);
                }
            }
        }
    }
    #pragma unroll
    for (int i=0;i<2;i++) {
        int y = y0 + 2*w + i;
        if (y >= H2) continue;
        int xA = x0 + g, xB = x0 + g + 8;
        bool vB = (xB < H2);
        #pragma unroll
        for (int nt=0; nt<8; nt++) {
            int co = nt*8 + 2*q4;
            size_t p0 = ((size_t)(n*CH + co    )*H2 + y)*H2;
            size_t p1 = ((size_t)(n*CH + co + 1)*H2 + y)*H2;
            g_Cf[p0 + xA] = acc[i][nt][0];
            g_Cf[p1 + xA] = acc[i][nt][1];
            if (vB) {
                g_Cf[p0 + xB] = acc[i][nt][2];
                g_Cf[p1 + xB] = acc[i][nt][3];
            }
        }
    }
}

// ---------------- conv3/conv4 (bf16 pre-split TC) @ 21x21, 1 tile/warp -------
__global__ void __launch_bounds__(256,3) conv34_tc(int which, const float* __restrict__ gamma,
                                                   const float* __restrict__ beta) {
    extern __shared__ uint32_t smu[];
    uint32_t* sInH = smu;                 // 4764 (529*9=4761 used, +3 pad)
    uint32_t* sInL = sInH + 4764;         // 4764
    uint32_t* sWh  = sInL + 4764;         // byte off 38112, %16==0
    uint32_t* sWl  = sWh + 4608;
    float* sc3 = (float*)(sWl + 4608);    // 64
    float* sh3 = sc3 + 64;                // 64  -> total 75488 B
    const float* src = which ? g_Cf : g_A;
    float* dst = which ? g_Bf : g_Cf;
    int n = blockIdx.y;
    int quarter = blockIdx.x;
    int grp = (n < NQIMG) ? 0 : 1;
    int tid = threadIdx.x;
    int w = tid >> 5, lane = tid & 31, g = lane >> 2, q4 = lane & 3;
    if (which && tid < 64) {
        float a, b;
        bn_sc(2, grp*64+tid, (float)LL, gamma[tid], beta[tid], a, b);
        sc3[tid] = a; sh3[tid] = b;
    }
    int t = quarter*7 + w;
    bool wact = (w < 7);
    int p0 = t*16 + g, p1 = p0 + 8;
    bool pv0 = wact && (p0 < LL), pv1 = wact && (p1 < LL);
    int py0 = p0/21, px0 = p0%21, py1 = p1/21, px1 = p1%21;
    float acc[8][4];
    #pragma unroll
    for (int nt=0;nt<8;nt++)
      #pragma unroll
      for (int r=0;r<4;r++) acc[nt][r]=0.f;
    const float* ibase = src + (size_t)n*CH*LL;
    const uint32_t* Wh = which ? g_W4h : g_W3h;
    const uint32_t* Wl = which ? g_W4l : g_W3l;
    for (int cc=0; cc<4; cc++) {
        __syncthreads();
        for (int i=tid; i<4232; i+=256) {
            int cp = i / 529, pos = i % 529;
            int yy = pos / 23, xx = pos % 23;
            int gy = yy - 1, gx = xx - 1;
            float v0 = 0.f, v1 = 0.f;
            if (gy>=0 && gy<H3 && gx>=0 && gx<H3) {
                const float* pp = ibase + (size_t)(cc*16 + 2*cp)*LL + gy*21 + gx;
                v0 = pp[0];
                v1 = pp[LL];
                if (which) {
                    int c0i = cc*16 + 2*cp;
                    v0 = lrelu(v0*sc3[c0i] + sh3[c0i]);
                    v1 = lrelu(v1*sc3[c0i+1] + sh3[c0i+1]);
                }
            }
            uint32_t hi, lo;
            split2(v0, v1, hi, lo);
            sInH[pos*9 + cp] = hi;
            sInL[pos*9 + cp] = lo;
        }
        {
            const uint4* sh = (const uint4*)(Wh + cc*4608);
            const uint4* sl = (const uint4*)(Wl + cc*4608);
            uint4* dh = (uint4*)sWh;
            uint4* dl = (uint4*)sWl;
            for (int i=tid; i<1152; i+=256) { dh[i]=sh[i]; dl[i]=sl[i]; }
        }
        __syncthreads();
        if (wact) {
            for (int s=0; s<9; s++) {
                int dy = s / 3, dx = s - 3*dy;
                uint32_t Ah[4] = {0,0,0,0}, Al[4] = {0,0,0,0};
                if (pv0) {
                    const uint32_t* pH = &sInH[((py0+dy)*23 + px0+dx)*9];
                    const uint32_t* pL = &sInL[((py0+dy)*23 + px0+dx)*9];
                    Ah[0] = pH[q4]; Ah[2] = pH[q4+4];
                    Al[0] = pL[q4]; Al[2] = pL[q4+4];
                }
                if (pv1) {
                    const uint32_t* pH = &sInH[((py1+dy)*23 + px1+dx)*9];
                    const uint32_t* pL = &sInL[((py1+dy)*23 + px1+dx)*9];
                    Ah[1] = pH[q4]; Ah[3] = pH[q4+4];
                    Al[1] = pL[q4]; Al[3] = pL[q4+4];
                }
                #pragma unroll
                for (int nt=0; nt<8; nt++) {
                    int wb = s*512 + nt*64 + lane*2;
                    uint32_t bh0 = sWh[wb], bh1 = sWh[wb+1];
                    uint32_t bl0 = sWl[wb], bl1 = sWl[wb+1];
                    MMA_BF16(acc[nt], Ah, bh0, bh1);
                    MMA_BF16(acc[nt], Ah, bl0, bl1);
                    MMA_BF16(acc[nt], Al, bh0, bh1);
                }
            }
        }
    }
    #pragma unroll
    for (int nt=0; nt<8; nt++) {
        int co = nt*8 + 2*q4;
        size_t b0 = ((size_t)n*CH + co    )*LL;
        size_t b1 = ((size_t)n*CH + co + 1)*LL;
        if (pv0) {
            dst[b0 + p0] = acc[nt][0];
            dst[b1 + p0] = acc[nt][1];
        }
        if (pv1) {
            dst[b0 + p1] = acc[nt][2];
            dst[b1 + p1] = acc[nt][3];
        }
    }
}

// ---------------- BN4 + LReLU + L2-normalize + tf32-round + transpose --------
__global__ void normalize_kernel(const float* __restrict__ gamma, const float* __restrict__ beta) {
    __shared__ float sc4[64], sh4[64];
    int n = blockIdx.y;
    int grp = (n < NQIMG) ? 0 : 1;
    if (threadIdx.x < 64) {
        float a, b;
        bn_sc(3, grp*64+threadIdx.x, (float)LL, gamma[threadIdx.x], beta[threadIdx.x], a, b);
        sc4[threadIdx.x] = a; sh4[threadIdx.x] = b;
    }
    __syncthreads();
    int l = blockIdx.x*256 + threadIdx.x;
    if (l >= LL) return;
    float v[64];
    float ss = 0.f;
    const float* p = g_Bf + (size_t)n*CH*LL + l;
    #pragma unroll
    for (int c=0;c<64;c++) {
        float t = lrelu(p[(size_t)c*LL]*sc4[c] + sh4[c]);
        v[c] = t; ss += t*t;
    }
    float inv = 1.f / fmaxf(sqrtf(ss), 1e-12f);
    float* dstp;
    if (n < NQIMG) {
        dstp = &g_qn[((size_t)n*LL + l)*64];
    } else {
        int ns = n - NQIMG;
        int b = ns/25, w = (ns%25)/5, s = ns%5;
        dstp = &g_sn[(((size_t)(b*5+w))*MM + (size_t)s*LL + l)*64];
    }
    #pragma unroll
    for (int c=0;c<64;c++) {
        float o = v[c]*inv;
        uint32_t ot;
        asm("cvt.rna.tf32.f32 %0, %1;" : "=r"(ot) : "f"(o));
        dstp[c] = __uint_as_float(ot);
    }
}

// ---------------- similarity: tf32 mma, 2 queries/block, prescreened top-3 ---
__global__ void __launch_bounds__(256,2) sim_kernel(float* __restrict__ out) {
    extern __shared__ float smem[];
    float* sQ  = smem;            // 2*64*68 = 8704
    float* sS  = sQ + 8704;       // 64*68 = 4352
    float* smg = sS + 4352;       // 2*64*2*3 = 768
    float* bs  = smg + 768;       // 2
    int lt = blockIdx.x;
    int bc = blockIdx.y;
    int b = bc/40; int qp = (bc/5)%8; int c = bc%5;
    const float* sb = g_sn + ((size_t)(b*5+c))*MM*64;
    int tid = threadIdx.x;
    int w = tid >> 5, lane = tid & 31;
    int g = lane >> 2, q4 = lane & 3;
    int rg = w & 3, cg = w >> 2;
    #pragma unroll
    for (int qq=0; qq<2; qq++) {
        const float* qb = g_qn + ((size_t)(b*16 + qp*2 + qq))*LL*64;
        int row = tid >> 2; int col = (tid & 3) << 4;
        int grow = lt*64 + row;
        float4* d4 = (float4*)&sQ[qq*4352 + row*68 + col];
        if (grow < LL) {
            const float4* s4 = (const float4*)(qb + (size_t)grow*64 + col);
            d4[0]=s4[0]; d4[1]=s4[1]; d4[2]=s4[2]; d4[3]=s4[3];
        } else {
            float4 z = {0,0,0,0};
            d4[0]=z; d4[1]=z; d4[2]=z; d4[3]=z;
        }
    }
    if (tid < 2) bs[tid] = 0.f;
    __syncthreads();
    int r0 = rg*16;
    unsigned afr[2][8][4];
    #pragma unroll
    for (int qq=0; qq<2; qq++) {
        const float* qa = &sQ[qq*4352 + (r0+g)*68 + q4];
        #pragma unroll
        for (int kc=0;kc<8;kc++) {
            afr[qq][kc][0] = __float_as_uint(qa[kc*8]);
            afr[qq][kc][1] = __float_as_uint(qa[8*68 + kc*8]);
            afr[qq][kc][2] = __float_as_uint(qa[kc*8 + 4]);
            afr[qq][kc][3] = __float_as_uint(qa[8*68 + kc*8 + 4]);
        }
    }
    float top[2][2][3];
    #pragma unroll
    for (int qq=0;qq<2;qq++)
      #pragma unroll
      for (int h=0;h<2;h++)
        #pragma unroll
        for (int k=0;k<3;k++) top[qq][h][k] = -1e30f;
    int n0 = cg*32;
    for (int mt=0; mt<35; mt++) {
        __syncthreads();
        {
            int row = tid >> 2; int col = (tid & 3) << 4;
            int m = mt*64 + row;
            float4* d4 = (float4*)&sS[row*68 + col];
            if (m < MM) {
                const float4* s4 = (const float4*)(sb + (size_t)m*64 + col);
                d4[0]=s4[0]; d4[1]=s4[1]; d4[2]=s4[2]; d4[3]=s4[3];
            } else {
                float4 z = {0,0,0,0};
                d4[0]=z; d4[1]=z; d4[2]=z; d4[3]=z;
            }
        }
        __syncthreads();
        bool tail = (mt == 34);
        #pragma unroll
        for (int nt=0; nt<4; nt++) {
            float C0[4] = {0,0,0,0};
            float C1[4] = {0,0,0,0};
            const float* pB = &sS[(n0 + nt*8 + g)*68 + q4];
            #pragma unroll
            for (int kc=0;kc<8;kc++) {
                unsigned bb0 = __float_as_uint(pB[kc*8]);
                unsigned bb1 = __float_as_uint(pB[kc*8 + 4]);
                MMA_TF32(C0, afr[0][kc], bb0, bb1);
                MMA_TF32(C1, afr[1][kc], bb0, bb1);
            }
            if (tail) {
                int col0 = mt*64 + n0 + nt*8 + (q4<<1);
                if (col0 < MM) {
                    ins3(C0[0], top[0][0][0], top[0][0][1], top[0][0][2]);
                    ins3(C0[2], top[0][1][0], top[0][1][1], top[0][1][2]);
                    ins3(C1[0], top[1][0][0], top[1][0][1], top[1][0][2]);
                    ins3(C1[2], top[1][1][0], top[1][1][1], top[1][1][2]);
                }
                if (col0+1 < MM) {
                    ins3(C0[1], top[0][0][0], top[0][0][1], top[0][0][2]);
                    ins3(C0[3], top[0][1][0], top[0][1][1], top[0][1][2]);
                    ins3(C1[1], top[1][0][0], top[1][0][1], top[1][0][2]);
                    ins3(C1[3], top[1][1][0], top[1][1][1], top[1][1][2]);
                }
            } else {
                // prescreen: pairwise max vs current 3rd-best (rarely exceeded)
                if (fmaxf(C0[0], C0[1]) > top[0][0][2]) {
                    ins3(C0[0], top[0][0][0], top[0][0][1], top[0][0][2]);
                    ins3(C0[1], top[0][0][0], top[0][0][1], top[0][0][2]);
                }
                if (fmaxf(C0[2], C0[3]) > top[0][1][2]) {
                    ins3(C0[2], top[0][1][0], top[0][1][1], top[0][1][2]);
                    ins3(C0[3], top[0][1][0], top[0][1][1], top[0][1][2]);
                }
                if (fmaxf(C1[0], C1[1]) > top[1][0][2]) {
                    ins3(C1[0], top[1][0][0], top[1][0][1], top[1][0][2]);
                    ins3(C1[1], top[1][0][0], top[1][0][1], top[1][0][2]);
                }
                if (fmaxf(C1[2], C1[3]) > top[1][1][2]) {
                    ins3(C1[2], top[1][1][0], top[1][1][1], top[1][1][2]);
                    ins3(C1[3], top[1][1][0], top[1][1][1], top[1][1][2]);
                }
            }
        }
    }
    #pragma unroll
    for (int ofs=1; ofs<=2; ofs<<=1) {
        #pragma unroll
        for (int qq=0;qq<2;qq++)
          #pragma unroll
          for (int h=0;h<2;h++) {
            float o0 = __shfl_xor_sync(0xffffffffu, top[qq][h][0], ofs);
            float o1 = __shfl_xor_sync(0xffffffffu, top[qq][h][1], ofs);
            float o2 = __shfl_xor_sync(0xffffffffu, top[qq][h][2], ofs);
            ins3(o0, top[qq][h][0], top[qq][h][1], top[qq][h][2]);
            ins3(o1, top[qq][h][0], top[qq][h][1], top[qq][h][2]);
            ins3(o2, top[qq][h][0], top[qq][h][1], top[qq][h][2]);
          }
    }
    if (q4 == 0) {
        #pragma unroll
        for (int qq=0;qq<2;qq++) {
            int rA = r0 + g;
            #pragma unroll
            for (int k=0;k<3;k++) {
                smg[((qq*64 + rA    )*2 + cg)*3 + k] = top[qq][0][k];
                smg[((qq*64 + rA + 8)*2 + cg)*3 + k] = top[qq][1][k];
            }
        }
    }
    __syncthreads();
    if (tid < 128) {
        int qq = tid >> 6, row = tid & 63;
        float m0 = smg[((qq*64+row)*2+0)*3+0];
        float m1 = smg[((qq*64+row)*2+0)*3+1];
        float m2 = smg[((qq*64+row)*2+0)*3+2];
        ins3(smg[((qq*64+row)*2+1)*3+0], m0,m1,m2);
        ins3(smg[((qq*64+row)*2+1)*3+1], m0,m1,m2);
        ins3(smg[((qq*64+row)*2+1)*3+2], m0,m1,m2);
        if (lt*64 + row < LL) atomicAdd(&bs[qq], m0+m1+m2);
    }
    __syncthreads();
    if (tid < 2) atomicAdd(&out[(b*16 + qp*2 + tid)*5 + c], bs[tid]);
}

// ---------------- launcher ----------------
extern "C" void kernel_launch(void* const* d_in, const int* in_sizes, int n_in,
                              void* d_out, int out_size) {
    const float* query   = (const float*)d_in[0];
    const float* support = (const float*)d_in[1];
    const float* W1 = (const float*)d_in[2];
    const float* g1 = (const float*)d_in[3];
    const float* b1 = (const float*)d_in[4];
    const float* W2 = (const float*)d_in[5];
    const float* g2 = (const float*)d_in[6];
    const float* b2 = (const float*)d_in[7];
    const float* W3 = (const float*)d_in[8];
    const float* g3 = (const float*)d_in[9];
    const float* b3 = (const float*)d_in[10];
    const float* W4 = (const float*)d_in[11];
    const float* g4 = (const float*)d_in[12];
    const float* b4 = (const float*)d_in[13];
    float* out = (float*)d_out;

    cudaFuncSetAttribute(conv2_tc, cudaFuncAttributeMaxDynamicSharedMemorySize, 60192);
    cudaFuncSetAttribute(conv34_tc, cudaFuncAttributeMaxDynamicSharedMemorySize, 75488);
    cudaFuncSetAttribute(sim_kernel, cudaFuncAttributeMaxDynamicSharedMemorySize, 55304);

    prep_kernel<<<224, 256>>>(out, W1, W2, W3, W4);

    // block 1: conv1 -> g_A -> stats L0 -> pool -> g_Bf
    conv1_kernel<<<dim3(36,2,NIMG), 256>>>(query, support);
    bn_part_kernel<<<dim3(128,16), 256>>>(0, H1*H1, 0);
    bn_pool0_pair<<<dim3(4, NIMG*CH), 256>>>(g1, b1);
    // block 2: g_Bf -> g_Cf (TC) -> stats L1 -> pool -> g_A
    conv2_tc<<<dim3(9,NIMG), 256, 60192>>>();
    bn_part_kernel<<<dim3(128,16), 256>>>(2, H2*H2, 1);
    bn_pool1<<<dim3(2, NIMG*CH), 256>>>(g2, b2);
    // block 3: g_A -> g_Cf (TC raw) -> stats L2
    conv34_tc<<<dim3(4,NIMG), 256, 75488>>>(0, g3, b3);
    bn_part_kernel<<<dim3(128,16), 256>>>(2, LL, 2);
    // block 4: g_Cf (BN L2 on read) -> g_Bf (TC) -> stats L3 -> normalize
    conv34_tc<<<dim3(4,NIMG), 256, 75488>>>(1, g3, b3);
    bn_part_kernel<<<dim3(128,16), 256>>>(1, LL, 3);
    normalize_kernel<<<dim3(2,NIMG), 256>>>(g4, b4);

    // cosine sim (tf32 tensor cores, 2 queries per block) + top-3 + sum
    sim_kernel<<<dim3(7,80), 256, 55304>>>(out);
}

// round 14
// speedup vs baseline: 1.0276x; 1.0276x over previous
#include <cuda_runtime.h>
#include <cuda_bf16.h>
#include <cstdint>

#define LRELU_SLOPE 0.2f
#define BN_EPS 1e-5f

#define NIMG 82
#define NQIMG 32
#define CH 64
#define H1 84
#define H2 42
#define H3 21
#define LL 441
#define MM 2205

// ---------------- scratch (device globals; no allocs allowed) ----------------
__device__ float g_A[(size_t)NIMG*CH*H1*H1];
__device__ float g_Bf[(size_t)NIMG*CH*H2*H2];
__device__ float g_Cf[(size_t)NIMG*CH*H2*H2];
__device__ float g_qn[(size_t)NQIMG*LL*CH];
__device__ float g_sn[(size_t)2*5*MM*CH];
__device__ float g_bnsum4[4*128*2];            // [layer][grp*64+c][{s,s2}]
__device__ float g_WT[64*9*64];                // conv1 weights [ci*9+k][co]
// bf16-split weight fragments: [cc(4)][s(9)][nt(8)][lane(32)][reg(2)]
__device__ uint32_t g_W2h[18432];
__device__ uint32_t g_W2l[18432];
__device__ uint32_t g_W3h[18432];
__device__ uint32_t g_W3l[18432];
__device__ uint32_t g_W4h[18432];
__device__ uint32_t g_W4l[18432];

__device__ __forceinline__ float lrelu(float x){ return x >= 0.f ? x : LRELU_SLOPE*x; }

__device__ __forceinline__ void ins3(float v, float& t0, float& t1, float& t2){
    if (v > t2) {
        float s  = fminf(t0, v);
        t0 = fmaxf(t0, v);
        float s2 = fminf(t1, s);
        t1 = fmaxf(t1, s);
        t2 = fmaxf(t2, s2);
    }
}

// split fp32 pair into bf16x2 hi + bf16x2 lo (v = hi + lo, error ~2^-18)
__device__ __forceinline__ void split2(float vx, float vy, uint32_t& hi, uint32_t& lo){
    __nv_bfloat162 h = __floats2bfloat162_rn(vx, vy);
    float hx = __bfloat162float(h.x);
    float hy = __bfloat162float(h.y);
    __nv_bfloat162 l = __floats2bfloat162_rn(vx - hx, vy - hy);
    hi = *reinterpret_cast<uint32_t*>(&h);
    lo = *reinterpret_cast<uint32_t*>(&l);
}

#define MMA_BF16(C, A, b0, b1) \
    asm volatile("mma.sync.aligned.m16n8k16.row.col.f32.bf16.bf16.f32 " \
        "{%0,%1,%2,%3},{%4,%5,%6,%7},{%8,%9},{%0,%1,%2,%3};" \
        : "+f"((C)[0]), "+f"((C)[1]), "+f"((C)[2]), "+f"((C)[3]) \
        : "r"((A)[0]), "r"((A)[1]), "r"((A)[2]), "r"((A)[3]), "r"(b0), "r"(b1))

#define MMA_TF32(C, A, b0, b1) \
    asm volatile("mma.sync.aligned.m16n8k8.row.col.f32.tf32.tf32.f32 " \
        "{%0,%1,%2,%3},{%4,%5,%6,%7},{%8,%9},{%0,%1,%2,%3};" \
        : "+f"((C)[0]), "+f"((C)[1]), "+f"((C)[2]), "+f"((C)[3]) \
        : "r"((A)[0]), "r"((A)[1]), "r"((A)[2]), "r"((A)[3]), "r"(b0), "r"(b1))

// BN scale/shift from per-layer raw sums
__device__ __forceinline__ void bn_sc(int layer, int gc, float HW, float gamma, float beta,
                                      float& sc, float& sh){
    float s  = g_bnsum4[(layer*128 + gc)*2 + 0];
    float s2 = g_bnsum4[(layer*128 + gc)*2 + 1];
    float cnt = ((gc >= 64) ? 50.f : 32.f) * HW;
    float mean = s / cnt;
    float var = s2 / cnt - mean*mean;
    float inv = rsqrtf(var + BN_EPS);
    sc = gamma * inv;
    sh = beta - mean * sc;
}

// ---------------- prep: zero + conv1 wtrans + conv2/3/4 frag pack ------------
__device__ __forceinline__ void frag_compute(const float* __restrict__ W, int i,
                                             uint32_t& hi, uint32_t& lo){
    int r  = i & 1;
    int t  = (i >> 1) & 31;
    int nt = (i >> 6) & 7;
    int rem = i >> 9;
    int s  = rem % 9;
    int cc = rem / 9;
    int q = t & 3, nn = t >> 2;
    int ci = cc*16 + 2*q + 8*r;
    int co = nt*8 + nn;
    float v0 = W[((size_t)co*64 + ci    )*9 + s];
    float v1 = W[((size_t)co*64 + ci + 1)*9 + s];
    split2(v0, v1, hi, lo);
}

__global__ void prep_kernel(float* out, const float* __restrict__ W1,
                            const float* __restrict__ W2, const float* __restrict__ W3,
                            const float* __restrict__ W4){
    int bx = blockIdx.x, tid = threadIdx.x;
    if (bx == 0) {
        if (tid < 160) out[tid] = 0.f;
        for (int i = tid; i < 4*128*2; i += 256) g_bnsum4[i] = 0.f;
    } else if (bx < 8) {
        int i = (bx-1)*256 + tid;
        if (i < 3*9*64) {
            int co = i & 63, r = i >> 6;
            int ci = r / 9, k = r % 9;
            g_WT[i] = W1[(size_t)co*3*9 + ci*9 + k];
        }
    } else if (bx < 80) {
        int i = (bx-8)*256 + tid;
        uint32_t hi, lo; frag_compute(W2, i, hi, lo);
        g_W2h[i] = hi; g_W2l[i] = lo;
    } else if (bx < 152) {
        int i = (bx-80)*256 + tid;
        uint32_t hi, lo; frag_compute(W3, i, hi, lo);
        g_W3h[i] = hi; g_W3l[i] = lo;
    } else {
        int i = (bx-152)*256 + tid;
        uint32_t hi, lo; frag_compute(W4, i, hi, lo);
        g_W4h[i] = hi; g_W4l[i] = lo;
    }
}

// ---------------- conv1: 3->64 @ 84x84, pad 1 (writes g_A) ----------------
__global__ void __launch_bounds__(256,3) conv1_kernel(const float* __restrict__ query,
                                                      const float* __restrict__ support) {
    __shared__ float swt[27*32];
    __shared__ float sin[3*18*18];
    int n = blockIdx.z, coH = blockIdx.y;
    int bx = blockIdx.x;
    int x0 = (bx % 6) * 16, y0 = (bx / 6) * 16;
    int tid = threadIdx.x;
    int tx = tid & 15, ty = tid >> 4;
    for (int i = tid; i < 864; i += 256) {
        int kk = i >> 5, co = i & 31;
        swt[i] = g_WT[kk*64 + coH*32 + co];
    }
    const float* img = (n < NQIMG) ? (query + (size_t)n*3*H1*H1)
                                   : (support + (size_t)(n-NQIMG)*3*H1*H1);
    for (int i = tid; i < 972; i += 256) {
        int ci = i / 324, rem = i % 324;
        int yy = rem / 18, xx = rem % 18;
        int gy = y0 - 1 + yy, gx = x0 - 1 + xx;
        sin[i] = (gy>=0 && gy<H1 && gx>=0 && gx<H1) ? img[(size_t)ci*H1*H1 + gy*H1 + gx] : 0.f;
    }
    __syncthreads();
    float r[27];
    #pragma unroll
    for (int ci=0;ci<3;ci++)
      #pragma unroll
      for (int dy=0;dy<3;dy++)
        #pragma unroll
        for (int dx=0;dx<3;dx++)
          r[ci*9+dy*3+dx] = sin[ci*324 + (ty+dy)*18 + (tx+dx)];
    float acc[32];
    #pragma unroll
    for (int i=0;i<32;i++) acc[i]=0.f;
    const float4* swt4 = (const float4*)swt;
    #pragma unroll
    for (int kk=0; kk<27; kk++) {
        float v = r[kk];
        #pragma unroll
        for (int c4=0; c4<8; c4++) {
            float4 w = swt4[kk*8 + c4];
            acc[c4*4+0] += w.x*v;
            acc[c4*4+1] += w.y*v;
            acc[c4*4+2] += w.z*v;
            acc[c4*4+3] += w.w*v;
        }
    }
    int y = y0+ty, x = x0+tx;
    if (y < H1 && x < H1) {
        size_t obase = ((size_t)n*CH + coH*32)*H1*H1 + (size_t)y*H1 + x;
        #pragma unroll 4
        for (int co=0; co<32; co++) g_A[obase + (size_t)co*H1*H1] = acc[co];
    }
}

// ---------------- BN partial stats -> g_bnsum4[layer] (8 slices) -------------
__global__ void bn_part_kernel(int srcSel, int HW, int layer){
    const float* src = (srcSel==0) ? g_A : (srcSel==1) ? g_Bf : g_Cf;
    int gc = blockIdx.x;
    int grp = gc >> 6, c = gc & 63;
    int slice = blockIdx.y;
    int n0, n1;
    if (!grp) { n0 = slice*4; n1 = n0+4; }
    else { n0 = 32 + (50*slice)/8; n1 = 32 + (50*(slice+1))/8; }
    float s = 0.f, s2 = 0.f;
    if ((HW & 3) == 0) {
        int m = HW >> 2;
        for (int n=n0; n<n1; n++) {
            const float4* p = (const float4*)(src + ((size_t)n*CH + c)*HW);
            for (int i=threadIdx.x; i<m; i+=256) {
                float4 v = p[i];
                s  += v.x + v.y + v.z + v.w;
                s2 += v.x*v.x + v.y*v.y + v.z*v.z + v.w*v.w;
            }
        }
    } else {
        for (int n=n0; n<n1; n++) {
            const float* p = src + ((size_t)n*CH + c)*HW;
            for (int i=threadIdx.x; i<HW; i+=256) {
                float v = p[i]; s += v; s2 += v*v;
            }
        }
    }
    __shared__ float sh1[256], sh2[256];
    sh1[threadIdx.x]=s; sh2[threadIdx.x]=s2;
    __syncthreads();
    for (int ofs=128; ofs>0; ofs>>=1) {
        if (threadIdx.x<ofs){ sh1[threadIdx.x]+=sh1[threadIdx.x+ofs]; sh2[threadIdx.x]+=sh2[threadIdx.x+ofs]; }
        __syncthreads();
    }
    if (threadIdx.x==0) {
        atomicAdd(&g_bnsum4[(layer*128+gc)*2+0], sh1[0]);
        atomicAdd(&g_bnsum4[(layer*128+gc)*2+1], sh2[0]);
    }
}

// ---------------- pool0: BN+LReLU+2x2 maxpool, 84->42, 2 outputs/thread ------
__global__ void bn_pool0_pair(const float* __restrict__ gamma, const float* __restrict__ beta) {
    int nc = blockIdx.y;
    int n = nc >> 6, c = nc & 63;
    int grp = (n < NQIMG) ? 0 : 1;
    float sc, sh;
    bn_sc(0, grp*64+c, (float)(H1*H1), gamma[c], beta[c], sc, sh);
    const float* base = g_A + (size_t)nc*H1*H1;
    float* obase = g_Bf + (size_t)nc*H2*H2;
    int idx = blockIdx.x*256 + threadIdx.x;      // 0..881 (42 rows x 21 col-pairs)
    if (idx >= 42*21) return;
    int y = idx / 21, xp = idx % 21;
    float4 a = *(const float4*)(base + (2*y)*H1 + 4*xp);
    float4 b = *(const float4*)(base + (2*y+1)*H1 + 4*xp);
    float o0 = fmaxf(fmaxf(lrelu(a.x*sc+sh), lrelu(a.y*sc+sh)),
                     fmaxf(lrelu(b.x*sc+sh), lrelu(b.y*sc+sh)));
    float o1 = fmaxf(fmaxf(lrelu(a.z*sc+sh), lrelu(a.w*sc+sh)),
                     fmaxf(lrelu(b.z*sc+sh), lrelu(b.w*sc+sh)));
    float2 o = {o0, o1};
    *(float2*)(obase + idx*2) = o;
}

// ---------------- pool1: BN+LReLU+2x2 maxpool, 42->21 -----------------------
__global__ void bn_pool1(const float* __restrict__ gamma, const float* __restrict__ beta) {
    int nc = blockIdx.y;
    int n = nc >> 6, c = nc & 63;
    int grp = (n < NQIMG) ? 0 : 1;
    float sc, sh;
    bn_sc(1, grp*64+c, (float)(H2*H2), gamma[c], beta[c], sc, sh);
    const float* base = g_Cf + (size_t)nc*H2*H2;
    float* obase = g_A + (size_t)nc*H3*H3;
    int idx = blockIdx.x*256 + threadIdx.x;
    if (idx >= H3*H3) return;
    int y = idx / H3, x = idx % H3;
    const float* p = base + (2*y)*H2 + 2*x;
    float2 r0 = *(const float2*)p;
    float2 r1 = *(const float2*)(p + H2);
    float a = lrelu(r0.x*sc+sh);
    float b = lrelu(r0.y*sc+sh);
    float c2 = lrelu(r1.x*sc+sh);
    float d = lrelu(r1.y*sc+sh);
    obase[idx] = fmaxf(fmaxf(a,b), fmaxf(c2,d));
}

// ---------------- conv2 (bf16 pre-split tensor core implicit GEMM) -----------
__global__ void __launch_bounds__(256,3) conv2_tc() {
    extern __shared__ uint32_t smu[];
    uint32_t* sInH = smu;                 // 2916
    uint32_t* sInL = sInH + 2916;         // 2916
    uint32_t* sWh  = sInL + 2916;         // 4608 (byte off 23328, %16==0)
    uint32_t* sWl  = sWh + 4608;          // 4608  -> total 60192 B
    int n = blockIdx.y;
    int bx = blockIdx.x;
    int x0 = (bx % 3) * 16, y0 = (bx / 3) * 16;
    int tid = threadIdx.x;
    int w = tid >> 5, lane = tid & 31, g = lane >> 2, q4 = lane & 3;
    float acc[2][8][4];
    #pragma unroll
    for (int i=0;i<2;i++)
      #pragma unroll
      for (int nt=0;nt<8;nt++)
        #pragma unroll
        for (int r=0;r<4;r++) acc[i][nt][r]=0.f;
    const float* ibase = g_Bf + (size_t)n*CH*H2*H2;
    for (int cc=0; cc<4; cc++) {
        __syncthreads();
        for (int i=tid; i<2592; i+=256) {
            int cp = i / 324, pos = i % 324;
            int yy = pos / 18, xx = pos % 18;
            int gy = y0 - 1 + yy, gx = x0 - 1 + xx;
            float v0 = 0.f, v1 = 0.f;
            if (gy>=0 && gy<H2 && gx>=0 && gx<H2) {
                const float* pp = ibase + (size_t)(cc*16 + 2*cp)*H2*H2 + gy*H2 + gx;
                v0 = pp[0];
                v1 = pp[H2*H2];
            }
            uint32_t hi, lo;
            split2(v0, v1, hi, lo);
            sInH[pos*9 + cp] = hi;
            sInL[pos*9 + cp] = lo;
        }
        {
            const uint4* sh = (const uint4*)(g_W2h + cc*4608);
            const uint4* sl = (const uint4*)(g_W2l + cc*4608);
            uint4* dh = (uint4*)sWh;
            uint4* dl = (uint4*)sWl;
            for (int i=tid; i<1152; i+=256) { dh[i]=sh[i]; dl[i]=sl[i]; }
        }
        __syncthreads();
        for (int s=0; s<9; s++) {
            int dy = s / 3, dx = s - 3*dy;
            uint32_t Ah[2][4], Al[2][4];
            #pragma unroll
            for (int i=0;i<2;i++) {
                int yy = 2*w + i + dy;
                const uint32_t* pH0 = &sInH[(yy*18 + g + dx)*9];
                const uint32_t* pH1 = &sInH[(yy*18 + g + 8 + dx)*9];
                const uint32_t* pL0 = &sInL[(yy*18 + g + dx)*9];
                const uint32_t* pL1 = &sInL[(yy*18 + g + 8 + dx)*9];
                Ah[i][0] = pH0[q4];   Ah[i][1] = pH1[q4];
                Ah[i][2] = pH0[q4+4]; Ah[i][3] = pH1[q4+4];
                Al[i][0] = pL0[q4];   Al[i][1] = pL1[q4];
                Al[i][2] = pL0[q4+4]; Al[i][3] = pL1[q4+4];
            }
            #pragma unroll
            for (int nt=0; nt<8; nt++) {
                int wb = s*512 + nt*64 + lane*2;
                uint32_t bh0 = sWh[wb], bh1 = sWh[wb+1];
                uint32_t bl0 = sWl[wb], bl1 = sWl[wb+1];
                #pragma unroll
                for (int i=0;i<2;i++) {
                    MMA_BF16(acc[i][nt], Ah[i], bh0, bh1);
                    MMA_BF16(acc[i][nt], Ah[i], bl0, bl1);
                    MMA_BF16(acc[i][nt], Al[i], bh0, bh1);
                }
            }
        }
    }
    #pragma unroll
    for (int i=0;i<2;i++) {
        int y = y0 + 2*w + i;
        if (y >= H2) continue;
        int xA = x0 + g, xB = x0 + g + 8;
        bool vB = (xB < H2);
        #pragma unroll
        for (int nt=0; nt<8; nt++) {
            int co = nt*8 + 2*q4;
            size_t p0 = ((size_t)(n*CH + co    )*H2 + y)*H2;
            size_t p1 = ((size_t)(n*CH + co + 1)*H2 + y)*H2;
            g_Cf[p0 + xA] = acc[i][nt][0];
            g_Cf[p1 + xA] = acc[i][nt][1];
            if (vB) {
                g_Cf[p0 + xB] = acc[i][nt][2];
                g_Cf[p1 + xB] = acc[i][nt][3];
            }
        }
    }
}

// ---------------- conv3/conv4 (bf16 pre-split TC) @ 21x21, 1 tile/warp -------
__global__ void __launch_bounds__(256,3) conv34_tc(int which, const float* __restrict__ gamma,
                                                   const float* __restrict__ beta) {
    extern __shared__ uint32_t smu[];
    uint32_t* sInH = smu;                 // 4764 (529*9=4761 used, +3 pad)
    uint32_t* sInL = sInH + 4764;         // 4764
    uint32_t* sWh  = sInL + 4764;         // byte off 38112, %16==0
    uint32_t* sWl  = sWh + 4608;
    float* sc3 = (float*)(sWl + 4608);    // 64
    float* sh3 = sc3 + 64;                // 64  -> total 75488 B
    const float* src = which ? g_Cf : g_A;
    float* dst = which ? g_Bf : g_Cf;
    int n = blockIdx.y;
    int quarter = blockIdx.x;
    int grp = (n < NQIMG) ? 0 : 1;
    int tid = threadIdx.x;
    int w = tid >> 5, lane = tid & 31, g = lane >> 2, q4 = lane & 3;
    if (which && tid < 64) {
        float a, b;
        bn_sc(2, grp*64+tid, (float)LL, gamma[tid], beta[tid], a, b);
        sc3[tid] = a; sh3[tid] = b;
    }
    int t = quarter*7 + w;
    bool wact = (w < 7);
    int p0 = t*16 + g, p1 = p0 + 8;
    bool pv0 = wact && (p0 < LL), pv1 = wact && (p1 < LL);
    int py0 = p0/21, px0 = p0%21, py1 = p1/21, px1 = p1%21;
    float acc[8][4];
    #pragma unroll
    for (int nt=0;nt<8;nt++)
      #pragma unroll
      for (int r=0;r<4;r++) acc[nt][r]=0.f;
    const float* ibase = src + (size_t)n*CH*LL;
    const uint32_t* Wh = which ? g_W4h : g_W3h;
    const uint32_t* Wl = which ? g_W4l : g_W3l;
    for (int cc=0; cc<4; cc++) {
        __syncthreads();
        for (int i=tid; i<4232; i+=256) {
            int cp = i / 529, pos = i % 529;
            int yy = pos / 23, xx = pos % 23;
            int gy = yy - 1, gx = xx - 1;
            float v0 = 0.f, v1 = 0.f;
            if (gy>=0 && gy<H3 && gx>=0 && gx<H3) {
                const float* pp = ibase + (size_t)(cc*16 + 2*cp)*LL + gy*21 + gx;
                v0 = pp[0];
                v1 = pp[LL];
                if (which) {
                    int c0i = cc*16 + 2*cp;
                    v0 = lrelu(v0*sc3[c0i] + sh3[c0i]);
                    v1 = lrelu(v1*sc3[c0i+1] + sh3[c0i+1]);
                }
            }
            uint32_t hi, lo;
            split2(v0, v1, hi, lo);
            sInH[pos*9 + cp] = hi;
            sInL[pos*9 + cp] = lo;
        }
        {
            const uint4* sh = (const uint4*)(Wh + cc*4608);
            const uint4* sl = (const uint4*)(Wl + cc*4608);
            uint4* dh = (uint4*)sWh;
            uint4* dl = (uint4*)sWl;
            for (int i=tid; i<1152; i+=256) { dh[i]=sh[i]; dl[i]=sl[i]; }
        }
        __syncthreads();
        if (wact) {
            for (int s=0; s<9; s++) {
                int dy = s / 3, dx = s - 3*dy;
                uint32_t Ah[4] = {0,0,0,0}, Al[4] = {0,0,0,0};
                if (pv0) {
                    const uint32_t* pH = &sInH[((py0+dy)*23 + px0+dx)*9];
                    const uint32_t* pL = &sInL[((py0+dy)*23 + px0+dx)*9];
                    Ah[0] = pH[q4]; Ah[2] = pH[q4+4];
                    Al[0] = pL[q4]; Al[2] = pL[q4+4];
                }
                if (pv1) {
                    const uint32_t* pH = &sInH[((py1+dy)*23 + px1+dx)*9];
                    const uint32_t* pL = &sInL[((py1+dy)*23 + px1+dx)*9];
                    Ah[1] = pH[q4]; Ah[3] = pH[q4+4];
                    Al[1] = pL[q4]; Al[3] = pL[q4+4];
                }
                #pragma unroll
                for (int nt=0; nt<8; nt++) {
                    int wb = s*512 + nt*64 + lane*2;
                    uint32_t bh0 = sWh[wb], bh1 = sWh[wb+1];
                    uint32_t bl0 = sWl[wb], bl1 = sWl[wb+1];
                    MMA_BF16(acc[nt], Ah, bh0, bh1);
                    MMA_BF16(acc[nt], Ah, bl0, bl1);
                    MMA_BF16(acc[nt], Al, bh0, bh1);
                }
            }
        }
    }
    #pragma unroll
    for (int nt=0; nt<8; nt++) {
        int co = nt*8 + 2*q4;
        size_t b0 = ((size_t)n*CH + co    )*LL;
        size_t b1 = ((size_t)n*CH + co + 1)*LL;
        if (pv0) {
            dst[b0 + p0] = acc[nt][0];
            dst[b1 + p0] = acc[nt][1];
        }
        if (pv1) {
            dst[b0 + p1] = acc[nt][2];
            dst[b1 + p1] = acc[nt][3];
        }
    }
}

// ---------------- BN4 + LReLU + L2-normalize + tf32-round + transpose --------
__global__ void normalize_kernel(const float* __restrict__ gamma, const float* __restrict__ beta) {
    __shared__ float sc4[64], sh4[64];
    int n = blockIdx.y;
    int grp = (n < NQIMG) ? 0 : 1;
    if (threadIdx.x < 64) {
        float a, b;
        bn_sc(3, grp*64+threadIdx.x, (float)LL, gamma[threadIdx.x], beta[threadIdx.x], a, b);
        sc4[threadIdx.x] = a; sh4[threadIdx.x] = b;
    }
    __syncthreads();
    int l = blockIdx.x*256 + threadIdx.x;
    if (l >= LL) return;
    float v[64];
    float ss = 0.f;
    const float* p = g_Bf + (size_t)n*CH*LL + l;
    #pragma unroll
    for (int c=0;c<64;c++) {
        float t = lrelu(p[(size_t)c*LL]*sc4[c] + sh4[c]);
        v[c] = t; ss += t*t;
    }
    float inv = 1.f / fmaxf(sqrtf(ss), 1e-12f);
    float* dstp;
    if (n < NQIMG) {
        dstp = &g_qn[((size_t)n*LL + l)*64];
    } else {
        int ns = n - NQIMG;
        int b = ns/25, w = (ns%25)/5, s = ns%5;
        dstp = &g_sn[(((size_t)(b*5+w))*MM + (size_t)s*LL + l)*64];
    }
    #pragma unroll
    for (int c=0;c<64;c++) {
        float o = v[c]*inv;
        uint32_t ot;
        asm("cvt.rna.tf32.f32 %0, %1;" : "=r"(ot) : "f"(o));
        dstp[c] = __uint_as_float(ot);
    }
}

// ---------------- similarity: tf32 mma, 2 queries/block ----------------
__global__ void __launch_bounds__(256,2) sim_kernel(float* __restrict__ out) {
    extern __shared__ float smem[];
    float* sQ  = smem;            // 2*64*68 = 8704
    float* sS  = sQ + 8704;       // 64*68 = 4352
    float* smg = sS + 4352;       // 2*64*2*3 = 768
    float* bs  = smg + 768;       // 2
    int lt = blockIdx.x;
    int bc = blockIdx.y;
    int b = bc/40; int qp = (bc/5)%8; int c = bc%5;
    const float* sb = g_sn + ((size_t)(b*5+c))*MM*64;
    int tid = threadIdx.x;
    int w = tid >> 5, lane = tid & 31;
    int g = lane >> 2, q4 = lane & 3;
    int rg = w & 3, cg = w >> 2;
    #pragma unroll
    for (int qq=0; qq<2; qq++) {
        const float* qb = g_qn + ((size_t)(b*16 + qp*2 + qq))*LL*64;
        int row = tid >> 2; int col = (tid & 3) << 4;
        int grow = lt*64 + row;
        float4* d4 = (float4*)&sQ[qq*4352 + row*68 + col];
        if (grow < LL) {
            const float4* s4 = (const float4*)(qb + (size_t)grow*64 + col);
            d4[0]=s4[0]; d4[1]=s4[1]; d4[2]=s4[2]; d4[3]=s4[3];
        } else {
            float4 z = {0,0,0,0};
            d4[0]=z; d4[1]=z; d4[2]=z; d4[3]=z;
        }
    }
    if (tid < 2) bs[tid] = 0.f;
    __syncthreads();
    int r0 = rg*16;
    unsigned afr[2][8][4];
    #pragma unroll
    for (int qq=0; qq<2; qq++) {
        const float* qa = &sQ[qq*4352 + (r0+g)*68 + q4];
        #pragma unroll
        for (int kc=0;kc<8;kc++) {
            afr[qq][kc][0] = __float_as_uint(qa[kc*8]);
            afr[qq][kc][1] = __float_as_uint(qa[8*68 + kc*8]);
            afr[qq][kc][2] = __float_as_uint(qa[kc*8 + 4]);
            afr[qq][kc][3] = __float_as_uint(qa[8*68 + kc*8 + 4]);
        }
    }
    float top[2][2][3];
    #pragma unroll
    for (int qq=0;qq<2;qq++)
      #pragma unroll
      for (int h=0;h<2;h++)
        #pragma unroll
        for (int k=0;k<3;k++) top[qq][h][k] = -1e30f;
    int n0 = cg*32;
    for (int mt=0; mt<35; mt++) {
        __syncthreads();
        {
            int row = tid >> 2; int col = (tid & 3) << 4;
            int m = mt*64 + row;
            float4* d4 = (float4*)&sS[row*68 + col];
            if (m < MM) {
                const float4* s4 = (const float4*)(sb + (size_t)m*64 + col);
                d4[0]=s4[0]; d4[1]=s4[1]; d4[2]=s4[2]; d4[3]=s4[3];
            } else {
                float4 z = {0,0,0,0};
                d4[0]=z; d4[1]=z; d4[2]=z; d4[3]=z;
            }
        }
        __syncthreads();
        bool tail = (mt == 34);
        #pragma unroll
        for (int nt=0; nt<4; nt++) {
            float C0[4] = {0,0,0,0};
            float C1[4] = {0,0,0,0};
            const float* pB = &sS[(n0 + nt*8 + g)*68 + q4];
            #pragma unroll
            for (int kc=0;kc<8;kc++) {
                unsigned bb0 = __float_as_uint(pB[kc*8]);
                unsigned bb1 = __float_as_uint(pB[kc*8 + 4]);
                MMA_TF32(C0, afr[0][kc], bb0, bb1);
                MMA_TF32(C1, afr[1][kc], bb0, bb1);
            }
            if (tail) {
                int col0 = mt*64 + n0 + nt*8 + (q4<<1);
                if (col0 < MM) {
                    ins3(C0[0], top[0][0][0], top[0][0][1], top[0][0][2]);
                    ins3(C0[2], top[0][1][0], top[0][1][1], top[0][1][2]);
                    ins3(C1[0], top[1][0][0], top[1][0][1], top[1][0][2]);
                    ins3(C1[2], top[1][1][0], top[1][1][1], top[1][1][2]);
                }
                if (col0+1 < MM) {
                    ins3(C0[1], top[0][0][0], top[0][0][1], top[0][0][2]);
                    ins3(C0[3], top[0][1][0], top[0][1][1], top[0][1][2]);
                    ins3(C1[1], top[1][0][0], top[1][0][1], top[1][0][2]);
                    ins3(C1[3], top[1][1][0], top[1][1][1], top[1][1][2]);
                }
            } else {
                ins3(C0[0], top[0][0][0], top[0][0][1], top[0][0][2]);
                ins3(C0[1], top[0][0][0], top[0][0][1], top[0][0][2]);
                ins3(C0[2], top[0][1][0], top[0][1][1], top[0][1][2]);
                ins3(C0[3], top[0][1][0], top[0][1][1], top[0][1][2]);
                ins3(C1[0], top[1][0][0], top[1][0][1], top[1][0][2]);
                ins3(C1[1], top[1][0][0], top[1][0][1], top[1][0][2]);
                ins3(C1[2], top[1][1][0], top[1][1][1], top[1][1][2]);
                ins3(C1[3], top[1][1][0], top[1][1][1], top[1][1][2]);
            }
        }
    }
    #pragma unroll
    for (int ofs=1; ofs<=2; ofs<<=1) {
        #pragma unroll
        for (int qq=0;qq<2;qq++)
          #pragma unroll
          for (int h=0;h<2;h++) {
            float o0 = __shfl_xor_sync(0xffffffffu, top[qq][h][0], ofs);
            float o1 = __shfl_xor_sync(0xffffffffu, top[qq][h][1], ofs);
            float o2 = __shfl_xor_sync(0xffffffffu, top[qq][h][2], ofs);
            ins3(o0, top[qq][h][0], top[qq][h][1], top[qq][h][2]);
            ins3(o1, top[qq][h][0], top[qq][h][1], top[qq][h][2]);
            ins3(o2, top[qq][h][0], top[qq][h][1], top[qq][h][2]);
          }
    }
    if (q4 == 0) {
        #pragma unroll
        for (int qq=0;qq<2;qq++) {
            int rA = r0 + g;
            #pragma unroll
            for (int k=0;k<3;k++) {
                smg[((qq*64 + rA    )*2 + cg)*3 + k] = top[qq][0][k];
                smg[((qq*64 + rA + 8)*2 + cg)*3 + k] = top[qq][1][k];
            }
        }
    }
    __syncthreads();
    if (tid < 128) {
        int qq = tid >> 6, row = tid & 63;
        float m0 = smg[((qq*64+row)*2+0)*3+0];
        float m1 = smg[((qq*64+row)*2+0)*3+1];
        float m2 = smg[((qq*64+row)*2+0)*3+2];
        ins3(smg[((qq*64+row)*2+1)*3+0], m0,m1,m2);
        ins3(smg[((qq*64+row)*2+1)*3+1], m0,m1,m2);
        ins3(smg[((qq*64+row)*2+1)*3+2], m0,m1,m2);
        if (lt*64 + row < LL) atomicAdd(&bs[qq], m0+m1+m2);
    }
    __syncthreads();
    if (tid < 2) atomicAdd(&out[(b*16 + qp*2 + tid)*5 + c], bs[tid]);
}

// ---------------- launcher ----------------
extern "C" void kernel_launch(void* const* d_in, const int* in_sizes, int n_in,
                              void* d_out, int out_size) {
    const float* query   = (const float*)d_in[0];
    const float* support = (const float*)d_in[1];
    const float* W1 = (const float*)d_in[2];
    const float* g1 = (const float*)d_in[3];
    const float* b1 = (const float*)d_in[4];
    const float* W2 = (const float*)d_in[5];
    const float* g2 = (const float*)d_in[6];
    const float* b2 = (const float*)d_in[7];
    const float* W3 = (const float*)d_in[8];
    const float* g3 = (const float*)d_in[9];
    const float* b3 = (const float*)d_in[10];
    const float* W4 = (const float*)d_in[11];
    const float* g4 = (const float*)d_in[12];
    const float* b4 = (const float*)d_in[13];
    float* out = (float*)d_out;

    cudaFuncSetAttribute(conv2_tc, cudaFuncAttributeMaxDynamicSharedMemorySize, 60192);
    cudaFuncSetAttribute(conv34_tc, cudaFuncAttributeMaxDynamicSharedMemorySize, 75488);
    cudaFuncSetAttribute(sim_kernel, cudaFuncAttributeMaxDynamicSharedMemorySize, 55304);

    prep_kernel<<<224, 256>>>(out, W1, W2, W3, W4);

    // block 1: conv1 -> g_A -> stats L0 -> pool -> g_Bf
    conv1_kernel<<<dim3(36,2,NIMG), 256>>>(query, support);
    bn_part_kernel<<<dim3(128,8), 256>>>(0, H1*H1, 0);
    bn_pool0_pair<<<dim3(4, NIMG*CH), 256>>>(g1, b1);
    // block 2: g_Bf -> g_Cf (TC) -> stats L1 -> pool -> g_A
    conv2_tc<<<dim3(9,NIMG), 256, 60192>>>();
    bn_part_kernel<<<dim3(128,8), 256>>>(2, H2*H2, 1);
    bn_pool1<<<dim3(2, NIMG*CH), 256>>>(g2, b2);
    // block 3: g_A -> g_Cf (TC raw) -> stats L2
    conv34_tc<<<dim3(4,NIMG), 256, 75488>>>(0, g3, b3);
    bn_part_kernel<<<dim3(128,8), 256>>>(2, LL, 2);
    // block 4: g_Cf (BN L2 on read) -> g_Bf (TC) -> stats L3 -> normalize
    conv34_tc<<<dim3(4,NIMG), 256, 75488>>>(1, g3, b3);
    bn_part_kernel<<<dim3(128,8), 256>>>(1, LL, 3);
    normalize_kernel<<<dim3(2,NIMG), 256>>>(g4, b4);

    // cosine sim (tf32 tensor cores, 2 queries per block) + top-3 + sum
    sim_kernel<<<dim3(7,80), 256, 55304>>>(out);
}